// round 2
// baseline (speedup 1.0000x reference)
#include <cuda_runtime.h>
#include <cuda_bf16.h>
#include <cstdint>

// Problem constants (fixed by the dataset)
#define N_NODES 100000
#define N_EDGES 800000

// Scratch (device globals; no allocation allowed). 16B-aligned for float4/red.v4.
__device__ __align__(16) float g_z1[(size_t)N_NODES * 64];    // layer1 pre-MLP accumulator
__device__ __align__(16) float g_h [(size_t)N_NODES * 128];   // layer1 output (post outer ReLU)
__device__ __align__(16) float g_z2[(size_t)N_NODES * 128];   // layer2 pre-MLP accumulator

// ---------------------------------------------------------------------------
// z = (1 + eps) * x   (vectorized copy-scale; eps read from device scalar)
// ---------------------------------------------------------------------------
__global__ void scale_copy_kernel(const float4* __restrict__ in,
                                  float4* __restrict__ out,
                                  const float* __restrict__ eps,
                                  int n4) {
    int i = blockIdx.x * blockDim.x + threadIdx.x;
    if (i >= n4) return;
    float s = 1.0f + *eps;
    float4 v = in[i];
    v.x *= s; v.y *= s; v.z *= s; v.w *= s;
    out[i] = v;
}

// ---------------------------------------------------------------------------
// Scatter-add: for each edge e, dst_acc[dst[e]] += src_feat[src[e]]
// D/4 threads per edge, each handling one float4 via red.global.add.v4.f32.
// NOTE: edge_index is int32 (JAX downcasts int64 without x64 mode).
// ---------------------------------------------------------------------------
template <int D>
__global__ void scatter_kernel(const int* __restrict__ ei,
                               const float* __restrict__ src_feat,
                               float* __restrict__ dst_acc,
                               int n_edges) {
    constexpr int TPE = D / 4;
    int tid = blockIdx.x * blockDim.x + threadIdx.x;
    int e = tid / TPE;
    if (e >= n_edges) return;
    int j = tid % TPE;
    int s = ei[e];
    int d = ei[n_edges + e];

    float4 v = reinterpret_cast<const float4*>(src_feat + (size_t)s * D)[j];
    float* p = dst_acc + (size_t)d * D + (size_t)j * 4;
    asm volatile("red.global.add.v4.f32 [%0], {%1, %2, %3, %4};"
                 :: "l"(p), "f"(v.x), "f"(v.y), "f"(v.z), "f"(v.w)
                 : "memory");
}

// ---------------------------------------------------------------------------
// Fused per-node MLP:  out = [relu] ( relu(z @ Wa + ba) @ Wb + bb )
// D_HID = 128 fixed. One warp per node; weights resident in dynamic smem.
// ---------------------------------------------------------------------------
template <int D_IN, int D_OUT, bool RELU_OUT>
__global__ void mlp_kernel(const float* __restrict__ z,
                           const float* __restrict__ Wa,
                           const float* __restrict__ ba,
                           const float* __restrict__ Wb,
                           const float* __restrict__ bb,
                           float* __restrict__ out,
                           int n_nodes) {
    constexpr int DH = 128;
    constexpr int CO = D_OUT / 32;       // cols per thread in output stage
    extern __shared__ float sm[];
    float* Wa_s = sm;                                  // D_IN * DH
    float* Wb_s = Wa_s + D_IN * DH;                    // DH * D_OUT
    float* ba_s = Wb_s + DH * D_OUT;                   // DH
    float* bb_s = ba_s + DH;                           // D_OUT
    float* z_s  = bb_s + D_OUT;                        // nwarps * D_IN
    const int nw = blockDim.x >> 5;
    float* h_s  = z_s + nw * D_IN;                     // nwarps * DH

    for (int i = threadIdx.x; i < D_IN * DH; i += blockDim.x) Wa_s[i] = Wa[i];
    for (int i = threadIdx.x; i < DH * D_OUT; i += blockDim.x) Wb_s[i] = Wb[i];
    for (int i = threadIdx.x; i < DH; i += blockDim.x) ba_s[i] = ba[i];
    for (int i = threadIdx.x; i < D_OUT; i += blockDim.x) bb_s[i] = bb[i];
    __syncthreads();

    const int warp = threadIdx.x >> 5;
    const int lane = threadIdx.x & 31;
    float* zw = z_s + warp * D_IN;
    float* hw = h_s + warp * DH;

    for (int node = blockIdx.x * nw + warp; node < n_nodes; node += gridDim.x * nw) {
        // load this node's z row into smem (float4-coalesced)
        if (lane < D_IN / 4)
            reinterpret_cast<float4*>(zw)[lane] =
                reinterpret_cast<const float4*>(z + (size_t)node * D_IN)[lane];
        __syncwarp();

        // hidden = relu(z @ Wa + ba); thread handles cols [4*lane, 4*lane+3]
        float4 acc = reinterpret_cast<const float4*>(ba_s)[lane];
        #pragma unroll 8
        for (int k = 0; k < D_IN; k++) {
            float zk = zw[k];
            float4 w = reinterpret_cast<const float4*>(Wa_s + k * DH)[lane];
            acc.x = fmaf(zk, w.x, acc.x);
            acc.y = fmaf(zk, w.y, acc.y);
            acc.z = fmaf(zk, w.z, acc.z);
            acc.w = fmaf(zk, w.w, acc.w);
        }
        acc.x = fmaxf(acc.x, 0.0f);
        acc.y = fmaxf(acc.y, 0.0f);
        acc.z = fmaxf(acc.z, 0.0f);
        acc.w = fmaxf(acc.w, 0.0f);
        reinterpret_cast<float4*>(hw)[lane] = acc;
        __syncwarp();

        // out = hidden @ Wb + bb; thread handles cols [CO*lane, CO*lane+CO-1]
        float o[CO];
        #pragma unroll
        for (int j = 0; j < CO; j++) o[j] = bb_s[lane * CO + j];
        #pragma unroll 8
        for (int k = 0; k < DH; k++) {
            float hk = hw[k];
            if constexpr (CO == 4) {
                float4 w = reinterpret_cast<const float4*>(Wb_s + k * D_OUT)[lane];
                o[0] = fmaf(hk, w.x, o[0]);
                o[1] = fmaf(hk, w.y, o[1]);
                o[2] = fmaf(hk, w.z, o[2]);
                o[3] = fmaf(hk, w.w, o[3]);
            } else {
                float2 w = reinterpret_cast<const float2*>(Wb_s + k * D_OUT)[lane];
                o[0] = fmaf(hk, w.x, o[0]);
                o[1] = fmaf(hk, w.y, o[1]);
            }
        }
        if (RELU_OUT) {
            #pragma unroll
            for (int j = 0; j < CO; j++) o[j] = fmaxf(o[j], 0.0f);
        }
        if constexpr (CO == 4) {
            float4 v = make_float4(o[0], o[1], o[2], o[3]);
            reinterpret_cast<float4*>(out + (size_t)node * D_OUT)[lane] = v;
        } else {
            float2 v = make_float2(o[0], o[1]);
            reinterpret_cast<float2*>(out + (size_t)node * D_OUT)[lane] = v;
        }
        __syncwarp();   // protect zw/hw before next iteration
    }
}

// ---------------------------------------------------------------------------
// Launch
// ---------------------------------------------------------------------------
extern "C" void kernel_launch(void* const* d_in, const int* in_sizes, int n_in,
                              void* d_out, int out_size) {
    const float* x    = (const float*)d_in[0];
    const int*   ei   = (const int*)d_in[1];
    const float* eps1 = (const float*)d_in[2];
    const float* eps2 = (const float*)d_in[3];
    const float* W1a  = (const float*)d_in[4];
    const float* b1a  = (const float*)d_in[5];
    const float* W1b  = (const float*)d_in[6];
    const float* b1b  = (const float*)d_in[7];
    const float* W2a  = (const float*)d_in[8];
    const float* b2a  = (const float*)d_in[9];
    const float* W2b  = (const float*)d_in[10];
    const float* b2b  = (const float*)d_in[11];
    float* out = (float*)d_out;

    const int n_nodes = in_sizes[0] / 64;
    const int n_edges = in_sizes[1] / 2;

    float *z1, *h, *z2;
    cudaGetSymbolAddress((void**)&z1, g_z1);
    cudaGetSymbolAddress((void**)&h,  g_h);
    cudaGetSymbolAddress((void**)&z2, g_z2);

    // dynamic smem for the MLP kernels
    const int smem1 = (64 * 128 + 128 * 128 + 128 + 128 + 8 * 64 + 8 * 128) * 4;
    const int smem2 = (128 * 128 + 128 * 64 + 128 + 64 + 8 * 128 + 8 * 128) * 4;
    cudaFuncSetAttribute(mlp_kernel<64, 128, true>,
                         cudaFuncAttributeMaxDynamicSharedMemorySize, smem1);
    cudaFuncSetAttribute(mlp_kernel<128, 64, false>,
                         cudaFuncAttributeMaxDynamicSharedMemorySize, smem2);

    const int MLP_BLOCKS = 296;   // 2 CTAs/SM * 148 SMs, grid-stride over nodes

    // ---- Layer 1 ----
    {
        int n4 = n_nodes * 64 / 4;
        scale_copy_kernel<<<(n4 + 255) / 256, 256>>>(
            (const float4*)x, (float4*)z1, eps1, n4);

        int threads = n_edges * (64 / 4);
        scatter_kernel<64><<<(threads + 255) / 256, 256>>>(ei, x, z1, n_edges);

        mlp_kernel<64, 128, true><<<MLP_BLOCKS, 256, smem1>>>(
            z1, W1a, b1a, W1b, b1b, h, n_nodes);
    }

    // ---- Layer 2 ----
    {
        int n4 = n_nodes * 128 / 4;
        scale_copy_kernel<<<(n4 + 255) / 256, 256>>>(
            (const float4*)h, (float4*)z2, eps2, n4);

        int threads = n_edges * (128 / 4);
        scatter_kernel<128><<<(threads + 255) / 256, 256>>>(ei, h, z2, n_edges);

        mlp_kernel<128, 64, false><<<MLP_BLOCKS, 256, smem2>>>(
            z2, W2a, b2a, W2b, b2b, out, n_nodes);
    }
}

// round 4
// speedup vs baseline: 1.3303x; 1.3303x over previous
#include <cuda_runtime.h>
#include <cuda_bf16.h>
#include <cstdint>

#define N_NODES 100000
#define N_EDGES 800000

typedef unsigned long long ull;

// ------------------------- device scratch (no allocs) ------------------------
__device__ __align__(16) float g_z1[(size_t)N_NODES * 64];
__device__ __align__(16) float g_h [(size_t)N_NODES * 128];
__device__ __align__(16) float g_z2[(size_t)N_NODES * 128];
__device__ int g_cnt[N_NODES];
__device__ int g_off[N_NODES + 1];
__device__ int g_cur[N_NODES];
__device__ int g_esrc[N_EDGES];

// ------------------------------ f32x2 helpers --------------------------------
__device__ __forceinline__ ull dup2(float f) {
    ull r; unsigned u = __float_as_uint(f);
    asm("mov.b64 %0, {%1, %1};" : "=l"(r) : "r"(u));
    return r;
}
__device__ __forceinline__ float2 unpack2(ull v) {
    unsigned a, b;
    asm("mov.b64 {%0, %1}, %2;" : "=r"(a), "=r"(b) : "l"(v));
    return make_float2(__uint_as_float(a), __uint_as_float(b));
}
__device__ __forceinline__ void ffma2(ull& d, ull a, ull b) {
    asm("fma.rn.f32x2 %0, %1, %2, %0;" : "+l"(d) : "l"(a), "l"(b));
}

// ------------------------------ CSR build ------------------------------------
__global__ void zero_kernel(int* p, int n) {
    int i = blockIdx.x * blockDim.x + threadIdx.x;
    if (i < n) p[i] = 0;
}

__global__ void hist_kernel(const int* __restrict__ dst, int* __restrict__ cnt, int n_edges) {
    int e = blockIdx.x * blockDim.x + threadIdx.x;
    if (e < n_edges) atomicAdd(&cnt[dst[e]], 1);
}

__global__ void scan_kernel(const int* __restrict__ cnt, int* __restrict__ off,
                            int* __restrict__ cur, int n, int n_edges) {
    __shared__ int part[1024];
    int t = threadIdx.x;
    int ch = (n + 1023) / 1024;
    int lo = t * ch, hi = min(lo + ch, n);
    int s = 0;
    for (int i = lo; i < hi; i++) s += cnt[i];
    part[t] = s;
    __syncthreads();
    for (int d = 1; d < 1024; d <<= 1) {
        int v = (t >= d) ? part[t - d] : 0;
        __syncthreads();
        part[t] += v;
        __syncthreads();
    }
    int run = (t == 0) ? 0 : part[t - 1];
    for (int i = lo; i < hi; i++) {
        off[i] = run; cur[i] = run;
        run += cnt[i];
    }
    if (t == 0) off[n] = n_edges;
}

__global__ void fill_kernel(const int* __restrict__ src, const int* __restrict__ dst,
                            int* __restrict__ cur, int* __restrict__ esrc, int n_edges) {
    int e = blockIdx.x * blockDim.x + threadIdx.x;
    if (e >= n_edges) return;
    int d = dst[e];
    int p = atomicAdd(&cur[d], 1);
    esrc[p] = src[e];
}

// --------------------- gather aggregation:  z = (1+eps)x + sum ---------------
// D = 64: half-warp per node (16 lanes x float4)
__global__ void gather64_kernel(const float* __restrict__ x,
                                const int* __restrict__ off,
                                const int* __restrict__ esrc,
                                const float* __restrict__ eps,
                                float* __restrict__ z, int n_nodes) {
    int gwarp = (blockIdx.x * blockDim.x + threadIdx.x) >> 5;
    int lane = threadIdx.x & 31;
    int node = gwarp * 2 + (lane >> 4);
    int l = lane & 15;
    if (node >= n_nodes) return;
    float4 self = reinterpret_cast<const float4*>(x + (size_t)node * 64)[l];
    float4 acc = make_float4(0.f, 0.f, 0.f, 0.f);
    int e0 = off[node], e1 = off[node + 1];
    for (int e = e0; e < e1; e++) {
        int s = __ldg(&esrc[e]);
        float4 v = reinterpret_cast<const float4*>(x + (size_t)s * 64)[l];
        acc.x += v.x; acc.y += v.y; acc.z += v.z; acc.w += v.w;
    }
    float sc = 1.0f + *eps;
    float4 r = make_float4(fmaf(sc, self.x, acc.x), fmaf(sc, self.y, acc.y),
                           fmaf(sc, self.z, acc.z), fmaf(sc, self.w, acc.w));
    reinterpret_cast<float4*>(z + (size_t)node * 64)[l] = r;
}

// D = 128: full warp per node (32 lanes x float4)
__global__ void gather128_kernel(const float* __restrict__ h,
                                 const int* __restrict__ off,
                                 const int* __restrict__ esrc,
                                 const float* __restrict__ eps,
                                 float* __restrict__ z, int n_nodes) {
    int node = (blockIdx.x * blockDim.x + threadIdx.x) >> 5;
    int l = threadIdx.x & 31;
    if (node >= n_nodes) return;
    float4 self = reinterpret_cast<const float4*>(h + (size_t)node * 128)[l];
    float4 acc = make_float4(0.f, 0.f, 0.f, 0.f);
    int e0 = off[node], e1 = off[node + 1];
    for (int e = e0; e < e1; e++) {
        int s = __ldg(&esrc[e]);
        float4 v = reinterpret_cast<const float4*>(h + (size_t)s * 128)[l];
        acc.x += v.x; acc.y += v.y; acc.z += v.z; acc.w += v.w;
    }
    float sc = 1.0f + *eps;
    float4 r = make_float4(fmaf(sc, self.x, acc.x), fmaf(sc, self.y, acc.y),
                           fmaf(sc, self.z, acc.z), fmaf(sc, self.w, acc.w));
    reinterpret_cast<float4*>(z + (size_t)node * 128)[l] = r;
}

// ------------------- node-blocked fused MLP with fma.rn.f32x2 ----------------
// tile = 64 nodes, 256 threads.
// stage1: h = relu(z @ Wa + ba)   (64 x D_IN) @ (D_IN x 128)
// stage2: o = [relu](h @ Wb + bb) (64 x 128) @ (128 x D_OUT)
// z and h tiles stored k-major in smem, row pad 68 floats (272B = 17x16B keeps
// every row 16B-aligned), so a node-pair is one packed 64-bit broadcast load.
template <int D_IN, int D_OUT, bool RELU_OUT>
__global__ void __launch_bounds__(256, 1)
mlp_kernel(const float* __restrict__ z,
           const float* __restrict__ Wa, const float* __restrict__ ba,
           const float* __restrict__ Wb, const float* __restrict__ bb,
           float* __restrict__ out, int n_nodes) {
    constexpr int DH = 128;
    constexpr int PAD = 68;
    extern __shared__ float sm[];
    float* Wa_s = sm;                       // D_IN * DH
    float* Wb_s = Wa_s + D_IN * DH;         // DH * D_OUT
    float* ba_s = Wb_s + DH * D_OUT;        // DH
    float* bb_s = ba_s + DH;                // D_OUT
    float* zT   = bb_s + D_OUT;             // D_IN * PAD   (k-major)
    float* hT   = zT + D_IN * PAD;          // DH * PAD     (k-major)

    for (int i = threadIdx.x; i < D_IN * DH; i += 256) Wa_s[i] = Wa[i];
    for (int i = threadIdx.x; i < DH * D_OUT; i += 256) Wb_s[i] = Wb[i];
    if (threadIdx.x < DH) ba_s[threadIdx.x] = ba[threadIdx.x];
    if (threadIdx.x < D_OUT) bb_s[threadIdx.x] = bb[threadIdx.x];

    const int tile0 = blockIdx.x * 64;

    // load + transpose z tile into zT[k][node]
    for (int i = threadIdx.x; i < 64 * (D_IN / 4); i += 256) {
        int node = i / (D_IN / 4);
        int kc = i % (D_IN / 4);
        float4 v = (tile0 + node < n_nodes)
                 ? reinterpret_cast<const float4*>(z + (size_t)(tile0 + node) * D_IN)[kc]
                 : make_float4(0.f, 0.f, 0.f, 0.f);
        zT[(kc * 4 + 0) * PAD + node] = v.x;
        zT[(kc * 4 + 1) * PAD + node] = v.y;
        zT[(kc * 4 + 2) * PAD + node] = v.z;
        zT[(kc * 4 + 3) * PAD + node] = v.w;
    }
    __syncthreads();

    // ---- stage 1: 8 nodes x 4 cols per thread ----
    {
        const int tx = threadIdx.x & 31;
        const int ty = threadIdx.x >> 5;
        ull acc[4][4];
        {
            float4 b = *reinterpret_cast<const float4*>(ba_s + 4 * tx);
            ull b0 = dup2(b.x), b1 = dup2(b.y), b2 = dup2(b.z), b3 = dup2(b.w);
            #pragma unroll
            for (int p = 0; p < 4; p++) { acc[p][0] = b0; acc[p][1] = b1; acc[p][2] = b2; acc[p][3] = b3; }
        }
        #pragma unroll 4
        for (int k = 0; k < D_IN; k++) {
            const ulonglong2* zp = reinterpret_cast<const ulonglong2*>(zT + k * PAD + ty * 8);
            ulonglong2 za = zp[0], zb = zp[1];
            ull z2[4] = {za.x, za.y, zb.x, zb.y};
            float4 w = *reinterpret_cast<const float4*>(Wa_s + k * DH + 4 * tx);
            ull w0 = dup2(w.x), w1 = dup2(w.y), w2 = dup2(w.z), w3 = dup2(w.w);
            #pragma unroll
            for (int p = 0; p < 4; p++) {
                ffma2(acc[p][0], z2[p], w0);
                ffma2(acc[p][1], z2[p], w1);
                ffma2(acc[p][2], z2[p], w2);
                ffma2(acc[p][3], z2[p], w3);
            }
        }
        // relu + store to hT[col][node] as node-pair float2
        #pragma unroll
        for (int p = 0; p < 4; p++) {
            #pragma unroll
            for (int c = 0; c < 4; c++) {
                float2 v = unpack2(acc[p][c]);
                v.x = fmaxf(v.x, 0.f);
                v.y = fmaxf(v.y, 0.f);
                *reinterpret_cast<float2*>(hT + (4 * tx + c) * PAD + ty * 8 + 2 * p) = v;
            }
        }
    }
    __syncthreads();

    // ---- stage 2 ----
    {
        constexpr int CG = D_OUT / 4;        // col groups (32 or 16)
        constexpr int NG = 256 / CG;         // node groups (8 or 16)
        constexpr int NPG = 64 / NG;         // nodes per group (8 or 4)
        constexpr int NP = NPG / 2;          // node pairs (4 or 2)
        const int tx = threadIdx.x % CG;
        const int ty = threadIdx.x / CG;
        ull acc[NP][4];
        {
            float4 b = *reinterpret_cast<const float4*>(bb_s + 4 * tx);
            ull b0 = dup2(b.x), b1 = dup2(b.y), b2 = dup2(b.z), b3 = dup2(b.w);
            #pragma unroll
            for (int p = 0; p < NP; p++) { acc[p][0] = b0; acc[p][1] = b1; acc[p][2] = b2; acc[p][3] = b3; }
        }
        #pragma unroll 4
        for (int k = 0; k < DH; k++) {
            ull z2[NP];
            if constexpr (NP == 4) {
                const ulonglong2* zp = reinterpret_cast<const ulonglong2*>(hT + k * PAD + ty * NPG);
                ulonglong2 za = zp[0], zb = zp[1];
                z2[0] = za.x; z2[1] = za.y; z2[2] = zb.x; z2[3] = zb.y;
            } else {
                ulonglong2 za = *reinterpret_cast<const ulonglong2*>(hT + k * PAD + ty * NPG);
                z2[0] = za.x; z2[1] = za.y;
            }
            float4 w = *reinterpret_cast<const float4*>(Wb_s + k * D_OUT + 4 * tx);
            ull w0 = dup2(w.x), w1 = dup2(w.y), w2 = dup2(w.z), w3 = dup2(w.w);
            #pragma unroll
            for (int p = 0; p < NP; p++) {
                ffma2(acc[p][0], z2[p], w0);
                ffma2(acc[p][1], z2[p], w1);
                ffma2(acc[p][2], z2[p], w2);
                ffma2(acc[p][3], z2[p], w3);
            }
        }
        // store: per node one float4 of 4 consecutive cols
        #pragma unroll
        for (int p = 0; p < NP; p++) {
            float2 c0 = unpack2(acc[p][0]);
            float2 c1 = unpack2(acc[p][1]);
            float2 c2 = unpack2(acc[p][2]);
            float2 c3 = unpack2(acc[p][3]);
            #pragma unroll
            for (int half = 0; half < 2; half++) {
                int node = tile0 + ty * NPG + 2 * p + half;
                if (node >= n_nodes) continue;
                float4 v = half ? make_float4(c0.y, c1.y, c2.y, c3.y)
                                : make_float4(c0.x, c1.x, c2.x, c3.x);
                if (RELU_OUT) {
                    v.x = fmaxf(v.x, 0.f); v.y = fmaxf(v.y, 0.f);
                    v.z = fmaxf(v.z, 0.f); v.w = fmaxf(v.w, 0.f);
                }
                reinterpret_cast<float4*>(out + (size_t)node * D_OUT)[tx] = v;
            }
        }
    }
}

// ---------------------------------- launch -----------------------------------
extern "C" void kernel_launch(void* const* d_in, const int* in_sizes, int n_in,
                              void* d_out, int out_size) {
    const float* x    = (const float*)d_in[0];
    const int*   ei   = (const int*)d_in[1];
    const float* eps1 = (const float*)d_in[2];
    const float* eps2 = (const float*)d_in[3];
    const float* W1a  = (const float*)d_in[4];
    const float* b1a  = (const float*)d_in[5];
    const float* W1b  = (const float*)d_in[6];
    const float* b1b  = (const float*)d_in[7];
    const float* W2a  = (const float*)d_in[8];
    const float* b2a  = (const float*)d_in[9];
    const float* W2b  = (const float*)d_in[10];
    const float* b2b  = (const float*)d_in[11];
    float* out = (float*)d_out;

    const int n_nodes = in_sizes[0] / 64;
    const int n_edges = in_sizes[1] / 2;
    const int* src = ei;
    const int* dst = ei + n_edges;

    float *z1, *h, *z2;
    int *cnt, *off, *cur, *esrc;
    cudaGetSymbolAddress((void**)&z1, g_z1);
    cudaGetSymbolAddress((void**)&h,  g_h);
    cudaGetSymbolAddress((void**)&z2, g_z2);
    cudaGetSymbolAddress((void**)&cnt, g_cnt);
    cudaGetSymbolAddress((void**)&off, g_off);
    cudaGetSymbolAddress((void**)&cur, g_cur);
    cudaGetSymbolAddress((void**)&esrc, g_esrc);

    const int smem1 = (64 * 128 + 128 * 128 + 128 + 128 + 64 * 68 + 128 * 68) * 4;
    const int smem2 = (128 * 128 + 128 * 64 + 128 + 64 + 128 * 68 + 128 * 68) * 4;
    cudaFuncSetAttribute(mlp_kernel<64, 128, true>,
                         cudaFuncAttributeMaxDynamicSharedMemorySize, smem1);
    cudaFuncSetAttribute(mlp_kernel<128, 64, false>,
                         cudaFuncAttributeMaxDynamicSharedMemorySize, smem2);

    // ---- CSR build (per call; deterministic edge sets per node) ----
    zero_kernel<<<(n_nodes + 255) / 256, 256>>>(cnt, n_nodes);
    hist_kernel<<<(n_edges + 255) / 256, 256>>>(dst, cnt, n_edges);
    scan_kernel<<<1, 1024>>>(cnt, off, cur, n_nodes, n_edges);
    fill_kernel<<<(n_edges + 255) / 256, 256>>>(src, dst, cur, esrc, n_edges);

    const int mlp_blocks = (n_nodes + 63) / 64;

    // ---- layer 1 ----
    {
        int nwarps = (n_nodes + 1) / 2;             // 2 nodes per warp
        gather64_kernel<<<(nwarps * 32 + 255) / 256, 256>>>(x, off, esrc, eps1, z1, n_nodes);
        mlp_kernel<64, 128, true><<<mlp_blocks, 256, smem1>>>(z1, W1a, b1a, W1b, b1b, h, n_nodes);
    }

    // ---- layer 2 ----
    {
        gather128_kernel<<<(n_nodes * 32 + 255) / 256, 256>>>(h, off, esrc, eps2, z2, n_nodes);
        mlp_kernel<128, 64, false><<<mlp_blocks, 256, smem2>>>(z2, W2a, b2a, W2b, b2b, out, n_nodes);
    }
}

// round 5
// speedup vs baseline: 1.9385x; 1.4572x over previous
#include <cuda_runtime.h>
#include <cuda_bf16.h>
#include <cstdint>

#define N_NODES 100000
#define N_EDGES 800000
#define SCAN_CHUNK 400

typedef unsigned long long ull;

// ------------------------- device scratch (no allocs) ------------------------
__device__ __align__(16) float g_z1[(size_t)N_NODES * 64];
__device__ __align__(16) float g_h [(size_t)N_NODES * 128];
__device__ __align__(16) float g_z2[(size_t)N_NODES * 128];
__device__ int g_cnt[N_NODES];
__device__ int g_off[N_NODES + 1];
__device__ int g_cur[N_NODES];
__device__ int g_esrc[N_EDGES];
__device__ int g_bsum[512];
__device__ int g_bpre[512];

// ------------------------------ f32x2 helpers --------------------------------
__device__ __forceinline__ ull dup2(float f) {
    ull r; unsigned u = __float_as_uint(f);
    asm("mov.b64 %0, {%1, %1};" : "=l"(r) : "r"(u));
    return r;
}
__device__ __forceinline__ float2 unpack2(ull v) {
    unsigned a, b;
    asm("mov.b64 {%0, %1}, %2;" : "=r"(a), "=r"(b) : "l"(v));
    return make_float2(__uint_as_float(a), __uint_as_float(b));
}
__device__ __forceinline__ void ffma2(ull& d, ull a, ull b) {
    asm("fma.rn.f32x2 %0, %1, %2, %0;" : "+l"(d) : "l"(a), "l"(b));
}

// ------------------------------ CSR build ------------------------------------
__global__ void zero_kernel(int* p, int n) {
    int i = blockIdx.x * blockDim.x + threadIdx.x;
    if (i < n) p[i] = 0;
}

__global__ void hist_kernel(const int* __restrict__ dst, int* __restrict__ cnt, int n_edges) {
    int e = blockIdx.x * blockDim.x + threadIdx.x;
    if (e < n_edges) atomicAdd(&cnt[dst[e]], 1);
}

// partial sums: block b sums cnt[b*CHUNK .. b*CHUNK+CHUNK)
__global__ void scan_part_kernel(const int* __restrict__ cnt, int* __restrict__ bsum, int n) {
    __shared__ int red[256];
    int b = blockIdx.x, t = threadIdx.x;
    int s = 0;
    for (int i = t; i < SCAN_CHUNK; i += 256) {
        int idx = b * SCAN_CHUNK + i;
        if (idx < n) s += cnt[idx];
    }
    red[t] = s;
    __syncthreads();
    for (int d = 128; d > 0; d >>= 1) {
        if (t < d) red[t] += red[t + d];
        __syncthreads();
    }
    if (t == 0) bsum[b] = red[0];
}

// exclusive scan of block sums (single block, <=512 blocks padded in smem)
__global__ void scan_bsum_kernel(const int* __restrict__ bsum, int* __restrict__ bpre,
                                 int nblocks, int* __restrict__ off, int n, int n_edges) {
    __shared__ int s[512];
    int t = threadIdx.x;
    s[t] = (t < nblocks) ? bsum[t] : 0;
    s[t + 256] = (t + 256 < nblocks) ? bsum[t + 256] : 0;
    __syncthreads();
    for (int d = 1; d < 512; d <<= 1) {
        int v0 = (t >= d) ? s[t - d] : 0;
        int v1 = s[t + 256 - d];
        __syncthreads();
        s[t] += v0;
        s[t + 256] += v1;
        __syncthreads();
    }
    if (t < nblocks) bpre[t] = s[t] - bsum[t];                       // exclusive
    if (t + 256 < nblocks) bpre[t + 256] = s[t + 256] - bsum[t + 256];
    if (t == 0) off[n] = n_edges;
}

// per-block local scan + emit off/cur
__global__ void scan_emit_kernel(const int* __restrict__ cnt, const int* __restrict__ bpre,
                                 int* __restrict__ off, int* __restrict__ cur, int n) {
    __shared__ int s[512];
    int b = blockIdx.x, t = threadIdx.x;
    #pragma unroll
    for (int h = 0; h < 2; h++) {
        int i = t + h * 256;
        int idx = b * SCAN_CHUNK + i;
        s[i] = (i < SCAN_CHUNK && idx < n) ? cnt[idx] : 0;
    }
    __syncthreads();
    for (int d = 1; d < 512; d <<= 1) {
        int v0 = (t >= d) ? s[t - d] : 0;
        int v1 = s[t + 256 - d];
        __syncthreads();
        s[t] += v0;
        s[t + 256] += v1;
        __syncthreads();
    }
    int base = bpre[b];
    #pragma unroll
    for (int h = 0; h < 2; h++) {
        int i = t + h * 256;
        int idx = b * SCAN_CHUNK + i;
        if (i < SCAN_CHUNK && idx < n) {
            int excl = base + (i ? s[i - 1] : 0);
            off[idx] = excl;
            cur[idx] = excl;
        }
    }
}

__global__ void fill_kernel(const int* __restrict__ src, const int* __restrict__ dst,
                            int* __restrict__ cur, int* __restrict__ esrc, int n_edges) {
    int e = blockIdx.x * blockDim.x + threadIdx.x;
    if (e >= n_edges) return;
    int d = dst[e];
    int p = atomicAdd(&cur[d], 1);
    esrc[p] = src[e];
}

// --------------------- gather aggregation:  z = (1+eps)x + sum ---------------
__global__ void gather64_kernel(const float* __restrict__ x,
                                const int* __restrict__ off,
                                const int* __restrict__ esrc,
                                const float* __restrict__ eps,
                                float* __restrict__ z, int n_nodes) {
    int gwarp = (blockIdx.x * blockDim.x + threadIdx.x) >> 5;
    int lane = threadIdx.x & 31;
    int node = gwarp * 2 + (lane >> 4);
    int l = lane & 15;
    if (node >= n_nodes) return;
    float4 self = reinterpret_cast<const float4*>(x + (size_t)node * 64)[l];
    float4 acc = make_float4(0.f, 0.f, 0.f, 0.f);
    int e0 = off[node], e1 = off[node + 1];
    for (int e = e0; e < e1; e++) {
        int s = __ldg(&esrc[e]);
        float4 v = reinterpret_cast<const float4*>(x + (size_t)s * 64)[l];
        acc.x += v.x; acc.y += v.y; acc.z += v.z; acc.w += v.w;
    }
    float sc = 1.0f + *eps;
    float4 r = make_float4(fmaf(sc, self.x, acc.x), fmaf(sc, self.y, acc.y),
                           fmaf(sc, self.z, acc.z), fmaf(sc, self.w, acc.w));
    reinterpret_cast<float4*>(z + (size_t)node * 64)[l] = r;
}

__global__ void gather128_kernel(const float* __restrict__ h,
                                 const int* __restrict__ off,
                                 const int* __restrict__ esrc,
                                 const float* __restrict__ eps,
                                 float* __restrict__ z, int n_nodes) {
    int node = (blockIdx.x * blockDim.x + threadIdx.x) >> 5;
    int l = threadIdx.x & 31;
    if (node >= n_nodes) return;
    float4 self = reinterpret_cast<const float4*>(h + (size_t)node * 128)[l];
    float4 acc = make_float4(0.f, 0.f, 0.f, 0.f);
    int e0 = off[node], e1 = off[node + 1];
    for (int e = e0; e < e1; e++) {
        int s = __ldg(&esrc[e]);
        float4 v = reinterpret_cast<const float4*>(h + (size_t)s * 128)[l];
        acc.x += v.x; acc.y += v.y; acc.z += v.z; acc.w += v.w;
    }
    float sc = 1.0f + *eps;
    float4 r = make_float4(fmaf(sc, self.x, acc.x), fmaf(sc, self.y, acc.y),
                           fmaf(sc, self.z, acc.z), fmaf(sc, self.w, acc.w));
    reinterpret_cast<float4*>(z + (size_t)node * 128)[l] = r;
}

// ------------------- node-blocked fused MLP with fma.rn.f32x2 ----------------
// TILE nodes per CTA, 256 threads. z/h tiles k-major in smem, PAD=TILE+4
// (keeps every row 8B-aligned for packed ull broadcast loads, spreads banks).
template <int D_IN, int D_OUT, int TILE, bool RELU_OUT>
__global__ void __launch_bounds__(256, 1)
mlp_kernel(const float* __restrict__ z,
           const float* __restrict__ Wa, const float* __restrict__ ba,
           const float* __restrict__ Wb, const float* __restrict__ bb,
           float* __restrict__ out, int n_nodes) {
    constexpr int DH = 128;
    constexpr int PAD = TILE + 4;
    constexpr int NG1 = 8;             // stage1 node groups (256/32)
    constexpr int NPG1 = TILE / NG1;   // nodes per group
    constexpr int NP1 = NPG1 / 2;      // node pairs per thread
    constexpr int CG = D_OUT / 4;      // stage2 col groups
    constexpr int NG2 = 256 / CG;
    constexpr int NPG2 = TILE / NG2;
    constexpr int NP2 = NPG2 / 2;

    extern __shared__ float sm[];
    float* Wa_s = sm;                       // D_IN * DH
    float* Wb_s = Wa_s + D_IN * DH;         // DH * D_OUT
    float* ba_s = Wb_s + DH * D_OUT;        // DH
    float* bb_s = ba_s + DH;                // D_OUT
    float* zT   = bb_s + D_OUT;             // D_IN * PAD   (k-major)
    float* hT   = zT + D_IN * PAD;          // DH * PAD     (k-major)

    for (int i = threadIdx.x; i < D_IN * DH; i += 256) Wa_s[i] = Wa[i];
    for (int i = threadIdx.x; i < DH * D_OUT; i += 256) Wb_s[i] = Wb[i];
    if (threadIdx.x < DH) ba_s[threadIdx.x] = ba[threadIdx.x];
    if (threadIdx.x < D_OUT) bb_s[threadIdx.x] = bb[threadIdx.x];

    const int tile0 = blockIdx.x * TILE;

    // load + transpose z tile into zT[k][node]
    for (int i = threadIdx.x; i < TILE * (D_IN / 4); i += 256) {
        int node = i / (D_IN / 4);
        int kc = i % (D_IN / 4);
        float4 v = (tile0 + node < n_nodes)
                 ? reinterpret_cast<const float4*>(z + (size_t)(tile0 + node) * D_IN)[kc]
                 : make_float4(0.f, 0.f, 0.f, 0.f);
        zT[(kc * 4 + 0) * PAD + node] = v.x;
        zT[(kc * 4 + 1) * PAD + node] = v.y;
        zT[(kc * 4 + 2) * PAD + node] = v.z;
        zT[(kc * 4 + 3) * PAD + node] = v.w;
    }
    __syncthreads();

    // ---- stage 1: NPG1 nodes x 4 cols per thread ----
    {
        const int tx = threadIdx.x & 31;
        const int ty = threadIdx.x >> 5;
        const float* zrow0 = zT + ty * NPG1;
        ull acc[NP1][4];
        {
            float4 b = *reinterpret_cast<const float4*>(ba_s + 4 * tx);
            ull b0 = dup2(b.x), b1 = dup2(b.y), b2 = dup2(b.z), b3 = dup2(b.w);
            #pragma unroll
            for (int p = 0; p < NP1; p++) { acc[p][0] = b0; acc[p][1] = b1; acc[p][2] = b2; acc[p][3] = b3; }
        }
        #pragma unroll 4
        for (int k = 0; k < D_IN; k++) {
            ull zp[NP1];
            #pragma unroll
            for (int p = 0; p < NP1; p++)
                zp[p] = *reinterpret_cast<const ull*>(zrow0 + k * PAD + 2 * p);
            float4 w = *reinterpret_cast<const float4*>(Wa_s + k * DH + 4 * tx);
            ull w0 = dup2(w.x), w1 = dup2(w.y), w2 = dup2(w.z), w3 = dup2(w.w);
            #pragma unroll
            for (int p = 0; p < NP1; p++) {
                ffma2(acc[p][0], zp[p], w0);
                ffma2(acc[p][1], zp[p], w1);
                ffma2(acc[p][2], zp[p], w2);
                ffma2(acc[p][3], zp[p], w3);
            }
        }
        #pragma unroll
        for (int p = 0; p < NP1; p++) {
            #pragma unroll
            for (int c = 0; c < 4; c++) {
                float2 v = unpack2(acc[p][c]);
                v.x = fmaxf(v.x, 0.f);
                v.y = fmaxf(v.y, 0.f);
                *reinterpret_cast<float2*>(hT + (4 * tx + c) * PAD + ty * NPG1 + 2 * p) = v;
            }
        }
    }
    __syncthreads();

    // ---- stage 2: NPG2 nodes x 4 cols per thread ----
    {
        const int tx = threadIdx.x % CG;
        const int ty = threadIdx.x / CG;
        const float* hrow0 = hT + ty * NPG2;
        ull acc[NP2][4];
        {
            float4 b = *reinterpret_cast<const float4*>(bb_s + 4 * tx);
            ull b0 = dup2(b.x), b1 = dup2(b.y), b2 = dup2(b.z), b3 = dup2(b.w);
            #pragma unroll
            for (int p = 0; p < NP2; p++) { acc[p][0] = b0; acc[p][1] = b1; acc[p][2] = b2; acc[p][3] = b3; }
        }
        #pragma unroll 4
        for (int k = 0; k < DH; k++) {
            ull zp[NP2];
            #pragma unroll
            for (int p = 0; p < NP2; p++)
                zp[p] = *reinterpret_cast<const ull*>(hrow0 + k * PAD + 2 * p);
            float4 w = *reinterpret_cast<const float4*>(Wb_s + k * D_OUT + 4 * tx);
            ull w0 = dup2(w.x), w1 = dup2(w.y), w2 = dup2(w.z), w3 = dup2(w.w);
            #pragma unroll
            for (int p = 0; p < NP2; p++) {
                ffma2(acc[p][0], zp[p], w0);
                ffma2(acc[p][1], zp[p], w1);
                ffma2(acc[p][2], zp[p], w2);
                ffma2(acc[p][3], zp[p], w3);
            }
        }
        #pragma unroll
        for (int p = 0; p < NP2; p++) {
            float2 c0 = unpack2(acc[p][0]);
            float2 c1 = unpack2(acc[p][1]);
            float2 c2 = unpack2(acc[p][2]);
            float2 c3 = unpack2(acc[p][3]);
            #pragma unroll
            for (int half = 0; half < 2; half++) {
                int node = tile0 + ty * NPG2 + 2 * p + half;
                if (node >= n_nodes) continue;
                float4 v = half ? make_float4(c0.y, c1.y, c2.y, c3.y)
                                : make_float4(c0.x, c1.x, c2.x, c3.x);
                if (RELU_OUT) {
                    v.x = fmaxf(v.x, 0.f); v.y = fmaxf(v.y, 0.f);
                    v.z = fmaxf(v.z, 0.f); v.w = fmaxf(v.w, 0.f);
                }
                reinterpret_cast<float4*>(out + (size_t)node * D_OUT)[tx] = v;
            }
        }
    }
}

// ---------------------------------- launch -----------------------------------
extern "C" void kernel_launch(void* const* d_in, const int* in_sizes, int n_in,
                              void* d_out, int out_size) {
    const float* x    = (const float*)d_in[0];
    const int*   ei   = (const int*)d_in[1];
    const float* eps1 = (const float*)d_in[2];
    const float* eps2 = (const float*)d_in[3];
    const float* W1a  = (const float*)d_in[4];
    const float* b1a  = (const float*)d_in[5];
    const float* W1b  = (const float*)d_in[6];
    const float* b1b  = (const float*)d_in[7];
    const float* W2a  = (const float*)d_in[8];
    const float* b2a  = (const float*)d_in[9];
    const float* W2b  = (const float*)d_in[10];
    const float* b2b  = (const float*)d_in[11];
    float* out = (float*)d_out;

    const int n_nodes = in_sizes[0] / 64;
    const int n_edges = in_sizes[1] / 2;
    const int* src = ei;
    const int* dst = ei + n_edges;

    float *z1, *h, *z2;
    int *cnt, *off, *cur, *esrc, *bsum, *bpre;
    cudaGetSymbolAddress((void**)&z1, g_z1);
    cudaGetSymbolAddress((void**)&h,  g_h);
    cudaGetSymbolAddress((void**)&z2, g_z2);
    cudaGetSymbolAddress((void**)&cnt, g_cnt);
    cudaGetSymbolAddress((void**)&off, g_off);
    cudaGetSymbolAddress((void**)&cur, g_cur);
    cudaGetSymbolAddress((void**)&esrc, g_esrc);
    cudaGetSymbolAddress((void**)&bsum, g_bsum);
    cudaGetSymbolAddress((void**)&bpre, g_bpre);

    // smem: weights + biases + zT + hT  (TILE1=128 -> PAD 132, TILE2=96 -> PAD 100)
    const int smem1 = (64 * 128 + 128 * 128 + 128 + 128 + 64 * 132 + 128 * 132) * 4;
    const int smem2 = (128 * 128 + 128 * 64 + 128 + 64 + 128 * 100 + 128 * 100) * 4;
    cudaFuncSetAttribute(mlp_kernel<64, 128, 128, true>,
                         cudaFuncAttributeMaxDynamicSharedMemorySize, smem1);
    cudaFuncSetAttribute(mlp_kernel<128, 64, 96, false>,
                         cudaFuncAttributeMaxDynamicSharedMemorySize, smem2);

    // ---- CSR build ----
    const int nscan = (n_nodes + SCAN_CHUNK - 1) / SCAN_CHUNK;   // 250
    zero_kernel<<<(n_nodes + 255) / 256, 256>>>(cnt, n_nodes);
    hist_kernel<<<(n_edges + 255) / 256, 256>>>(dst, cnt, n_edges);
    scan_part_kernel<<<nscan, 256>>>(cnt, bsum, n_nodes);
    scan_bsum_kernel<<<1, 256>>>(bsum, bpre, nscan, off, n_nodes, n_edges);
    scan_emit_kernel<<<nscan, 256>>>(cnt, bpre, off, cur, n_nodes);
    fill_kernel<<<(n_edges + 255) / 256, 256>>>(src, dst, cur, esrc, n_edges);

    // ---- layer 1 ----
    {
        int nwarps = (n_nodes + 1) / 2;
        gather64_kernel<<<(nwarps * 32 + 255) / 256, 256>>>(x, off, esrc, eps1, z1, n_nodes);
        int blocks = (n_nodes + 127) / 128;
        mlp_kernel<64, 128, 128, true><<<blocks, 256, smem1>>>(z1, W1a, b1a, W1b, b1b, h, n_nodes);
    }

    // ---- layer 2 ----
    {
        gather128_kernel<<<(n_nodes * 32 + 255) / 256, 256>>>(h, off, esrc, eps2, z2, n_nodes);
        int blocks = (n_nodes + 95) / 96;
        mlp_kernel<128, 64, 96, false><<<blocks, 256, smem2>>>(z2, W2a, b2a, W2b, b2b, out, n_nodes);
    }
}